// round 5
// baseline (speedup 1.0000x reference)
#include <cuda_runtime.h>
#include <math.h>

#define BB   8192
#define DD   2048
#define EE   8
#define GG   4
#define PP   512
#define HH   192
#define PREDW 0.1

#define BM 64
#define BN 128
#define BK 16
#define HS 68          // Hs row stride (pad 64 -> 68)

// ---- device scratch (no allocations allowed in kernel_launch) ----
__device__ int   g_cnt[EE];
__device__ int   g_list[EE * BB];     // token + slot*8192
__device__ float g_wlist[EE * BB];
__device__ float g_scratch[(size_t)2 * BB * DD];   // 134 MB: per (token, slot) weighted expert output

__global__ void zero_cnt_kernel() {
    if (threadIdx.x < EE) g_cnt[threadIdx.x] = 0;
}

// ---------------- routing: qm -> phasor mean -> logits -> softmax -> top-2 ----------------
// Near-degenerate logits (spread ~1e-3, gaps ~3e-4) mean routing flips dominate
// rel_err. Everything on the scalar path is computed in double so that the only
// divergence from the fp32 reference is the reference's own rounding noise.
__global__ void routing_kernel(const float* __restrict__ x,
                               const float* __restrict__ Wg, const float* __restrict__ bg,
                               const float* __restrict__ Wp, const float* __restrict__ bp,
                               const float* __restrict__ Wgg, const float* __restrict__ bgg)
{
    int warp = threadIdx.x >> 5;
    int lane = threadIdx.x & 31;
    int b = blockIdx.x * 8 + warp;
    if (b >= BB) return;

    // exact row mean (double accumulation)
    const float4* xr = (const float4*)(x + (size_t)b * DD);
    double s = 0.0;
#pragma unroll 4
    for (int i = lane; i < DD / 4; i += 32) {
        float4 v = xr[i];
        s += ((double)v.x + (double)v.y) + ((double)v.z + (double)v.w);
    }
#pragma unroll
    for (int o = 16; o; o >>= 1) s += __shfl_xor_sync(0xffffffffu, s, o);
    float qm = (float)(s * (1.0 / DD));   // fp32, matches reference's qm to its own rounding noise

    // phasor bank: sum_{h=1..192} cos(ang)+sin(ang), ang quantized to fp32 like the reference
    double ts = 0.0;
#pragma unroll
    for (int j = 0; j < 6; j++) {
        float f = 7.0f * (float)(1 + lane + 32 * j);   // exactly representable
        float angf = qm * f;                            // fp32 product, same as reference
        double sn, cs;
        sincos((double)angf, &sn, &cs);                 // accurate trig of the fp32 angle
        ts += sn + cs;
    }
#pragma unroll
    for (int o = 16; o; o >>= 1) ts += __shfl_xor_sync(0xffffffffu, ts, o);

    if (lane != 0) return;

    double gi0 = ts * (1.0 / (2.0 * HH));
    double gi1 = 0.015625;   // KTOP/D — LIF spike rate is exactly 1 on top-K lanes, 0 elsewhere

    double l[EE];
#pragma unroll
    for (int e = 0; e < EE; e++) {
        int g = e & 3;
        double v = gi0 * (double)Wg[e] + gi1 * (double)Wg[EE + e] + (double)bg[e];
        v -= PREDW * (gi0 * (double)Wp[e] + gi1 * (double)Wp[EE + e] + (double)bp[e]);
        v += gi0 * (double)Wgg[g] + gi1 * (double)Wgg[GG + g] + (double)bgg[g];
        l[e] = v;
    }
    double mx = l[0];
#pragma unroll
    for (int e = 1; e < EE; e++) mx = fmax(mx, l[e]);
    double p[EE], sum = 0.0;
#pragma unroll
    for (int e = 0; e < EE; e++) { p[e] = exp(l[e] - mx); sum += p[e]; }
    double inv = 1.0 / sum;
#pragma unroll
    for (int e = 0; e < EE; e++) p[e] *= inv;

    // top-2, ties -> lowest index (matches jax.lax.top_k)
    int i1 = 0;
#pragma unroll
    for (int e = 1; e < EE; e++) if (p[e] > p[i1]) i1 = e;
    int i2 = (i1 == 0) ? 1 : 0;
#pragma unroll
    for (int e = 0; e < EE; e++) if (e != i1 && p[e] > p[i2]) i2 = e;

    double denom = p[i1] + p[i2] + 1e-9;
    float w1 = (float)(p[i1] / denom);
    float w2 = (float)(p[i2] / denom);

    int pos = atomicAdd(&g_cnt[i1], 1);
    g_list [i1 * BB + pos] = b;            // slot 0
    g_wlist[i1 * BB + pos] = w1;
    pos = atomicAdd(&g_cnt[i2], 1);
    g_list [i2 * BB + pos] = b + BB;       // slot 1
    g_wlist[i2 * BB + pos] = w2;
}

// ---------------- fused per-expert MLP: GEMM1 -> ReLU -> GEMM2 -> weight -> scratch ----------------
__global__ __launch_bounds__(256, 1)
void expert_kernel(const float* __restrict__ x,
                   const float* __restrict__ W1, const float* __restrict__ b1,
                   const float* __restrict__ W2, const float* __restrict__ b2)
{
    int e = blockIdx.y;
    int cnt = g_cnt[e];
    int t0 = blockIdx.x * BM;
    if (t0 >= cnt) return;
    int ntok = min(BM, cnt - t0);

    extern __shared__ float Hs[];                  // [PP][HS] transposed: Hs[p*HS + m]
    __shared__ float As[BK][BM];                   // A^T tile
    __shared__ float Bs[BK][BN];
    __shared__ int   s_tok[BM];
    __shared__ int   s_slot[BM];
    __shared__ float s_w[BM];

    int tid = threadIdx.x;
    if (tid < BM) {
        int idx = (tid < ntok) ? (t0 + tid) : t0;
        int entry = g_list[e * BB + idx];
        s_tok[tid]  = entry & (BB - 1);
        s_slot[tid] = entry >> 13;
        s_w[tid]    = (tid < ntok) ? g_wlist[e * BB + idx] : 0.f;
    }
    __syncthreads();

    const float* W1e = W1 + (size_t)e * DD * PP;
    const float* b1e = b1 + e * PP;
    const float* W2e = W2 + (size_t)e * PP * DD;
    const float* b2e = b2 + e * DD;

    int tx = tid & 15;            // n dim
    int ty = tid >> 4;            // m dim
    int m0 = ty * 4;
    int n0 = tx * 8;

    // A loader: thread -> (m = tid/4, k4 = (tid&3)*4)
    int la_m = tid >> 2;
    int la_k = (tid & 3) * 4;
    const float* xrow = x + (size_t)s_tok[la_m] * DD + la_k;
    // B loader: thread -> (k = tid/16, two float4 at n4 = tid%16 and 16+tid%16)
    int lb_k  = tid >> 4;
    int lb_n  = tid & 15;

    // ================= GEMM1: H = relu(X @ W1e + b1e) =================
    for (int nc = 0; nc < PP / BN; nc++) {
        float acc[4][8];
#pragma unroll
        for (int i = 0; i < 4; i++)
#pragma unroll
            for (int j = 0; j < 8; j++) acc[i][j] = 0.f;

        const float* Wbase = W1e + (size_t)lb_k * PP + nc * BN;
        for (int k0 = 0; k0 < DD; k0 += BK) {
            float4 av = *(const float4*)(xrow + k0);
            const float4* src = (const float4*)(Wbase + (size_t)k0 * PP);
            float4 bv0 = src[lb_n];
            float4 bv1 = src[16 + lb_n];
            As[la_k + 0][la_m] = av.x;
            As[la_k + 1][la_m] = av.y;
            As[la_k + 2][la_m] = av.z;
            As[la_k + 3][la_m] = av.w;
            *(float4*)&Bs[lb_k][lb_n * 4]      = bv0;
            *(float4*)&Bs[lb_k][64 + lb_n * 4] = bv1;
            __syncthreads();
#pragma unroll
            for (int k = 0; k < BK; k++) {
                float a[4], bb[8];
                *(float4*)a       = *(const float4*)&As[k][m0];
                *(float4*)&bb[0]  = *(const float4*)&Bs[k][n0];
                *(float4*)&bb[4]  = *(const float4*)&Bs[k][n0 + 4];
#pragma unroll
                for (int i = 0; i < 4; i++)
#pragma unroll
                    for (int j = 0; j < 8; j++) acc[i][j] = fmaf(a[i], bb[j], acc[i][j]);
            }
            __syncthreads();
        }
        // epilogue: relu(+bias) -> Hs[p][m] (transposed so GEMM2 A-reads are LDS.128)
#pragma unroll
        for (int j = 0; j < 8; j++) {
            int pcol = nc * BN + n0 + j;
            float bias = b1e[pcol];
#pragma unroll
            for (int i = 0; i < 4; i++) {
                Hs[pcol * HS + m0 + i] = fmaxf(acc[i][j] + bias, 0.f);
            }
        }
        __syncthreads();
    }

    // ================= GEMM2: out = (H @ W2e + b2e) * w -> scratch =================
    for (int nc = 0; nc < DD / BN; nc++) {
        float acc[4][8];
#pragma unroll
        for (int i = 0; i < 4; i++)
#pragma unroll
            for (int j = 0; j < 8; j++) acc[i][j] = 0.f;

        const float* Wbase = W2e + (size_t)lb_k * DD + nc * BN;
        for (int k0 = 0; k0 < PP; k0 += BK) {
            const float4* src = (const float4*)(Wbase + (size_t)k0 * DD);
            float4 bv0 = src[lb_n];
            float4 bv1 = src[16 + lb_n];
            __syncthreads();   // previous k-tile compute done before Bs overwrite
            *(float4*)&Bs[lb_k][lb_n * 4]      = bv0;
            *(float4*)&Bs[lb_k][64 + lb_n * 4] = bv1;
            __syncthreads();
#pragma unroll
            for (int k = 0; k < BK; k++) {
                float a[4], bb[8];
                *(float4*)a      = *(const float4*)&Hs[(k0 + k) * HS + m0];
                *(float4*)&bb[0] = *(const float4*)&Bs[k][n0];
                *(float4*)&bb[4] = *(const float4*)&Bs[k][n0 + 4];
#pragma unroll
                for (int i = 0; i < 4; i++)
#pragma unroll
                    for (int j = 0; j < 8; j++) acc[i][j] = fmaf(a[i], bb[j], acc[i][j]);
            }
        }
        // epilogue: (+bias)*gate_weight -> scratch[(token*2+slot)][d]
#pragma unroll
        for (int i = 0; i < 4; i++) {
            int m = m0 + i;
            if (m < ntok) {
                float w = s_w[m];
                size_t row = ((size_t)(s_tok[m] * 2 + s_slot[m])) * DD + nc * BN + n0;
                float4 o0, o1;
                o0.x = (acc[i][0] + b2e[nc * BN + n0 + 0]) * w;
                o0.y = (acc[i][1] + b2e[nc * BN + n0 + 1]) * w;
                o0.z = (acc[i][2] + b2e[nc * BN + n0 + 2]) * w;
                o0.w = (acc[i][3] + b2e[nc * BN + n0 + 3]) * w;
                o1.x = (acc[i][4] + b2e[nc * BN + n0 + 4]) * w;
                o1.y = (acc[i][5] + b2e[nc * BN + n0 + 5]) * w;
                o1.z = (acc[i][6] + b2e[nc * BN + n0 + 6]) * w;
                o1.w = (acc[i][7] + b2e[nc * BN + n0 + 7]) * w;
                *(float4*)&g_scratch[row]     = o0;
                *(float4*)&g_scratch[row + 4] = o1;
            }
        }
    }
}

// ---------------- combine: out[b] = scr[b, slot0] + scr[b, slot1] ----------------
__global__ void combine_kernel(float* __restrict__ out)
{
    size_t i = (size_t)blockIdx.x * blockDim.x + threadIdx.x;   // float4 index over B*D/4
    size_t b = i / (DD / 4);
    size_t c = i - b * (DD / 4);
    const float4* s = (const float4*)g_scratch;
    float4 a0 = s[(2 * b)     * (DD / 4) + c];
    float4 a1 = s[(2 * b + 1) * (DD / 4) + c];
    float4 o;
    o.x = a0.x + a1.x; o.y = a0.y + a1.y; o.z = a0.z + a1.z; o.w = a0.w + a1.w;
    ((float4*)out)[i] = o;
}

extern "C" void kernel_launch(void* const* d_in, const int* in_sizes, int n_in,
                              void* d_out, int out_size)
{
    const float* x   = (const float*)d_in[0];
    const float* Wg  = (const float*)d_in[1];
    const float* bg  = (const float*)d_in[2];
    const float* Wp  = (const float*)d_in[3];
    const float* bp  = (const float*)d_in[4];
    const float* Wgg = (const float*)d_in[5];
    const float* bgg = (const float*)d_in[6];
    const float* W1  = (const float*)d_in[7];
    const float* b1  = (const float*)d_in[8];
    const float* W2  = (const float*)d_in[9];
    const float* b2  = (const float*)d_in[10];
    float* out = (float*)d_out;

    cudaFuncSetAttribute(expert_kernel, cudaFuncAttributeMaxDynamicSharedMemorySize,
                         PP * HS * (int)sizeof(float));

    zero_cnt_kernel<<<1, 32>>>();
    routing_kernel<<<BB / 8, 256>>>(x, Wg, bg, Wp, bp, Wgg, bgg);
    expert_kernel<<<dim3(BB / BM, EE), 256, PP * HS * sizeof(float)>>>(x, W1, b1, W2, b2);
    combine_kernel<<<(BB * (DD / 4)) / 256, 256>>>(out);
    (void)in_sizes; (void)n_in; (void)out_size;
}

// round 10
// speedup vs baseline: 1.7313x; 1.7313x over previous
#include <cuda_runtime.h>
#include <math.h>
#include <stdint.h>

#define BB   8192
#define DD   2048
#define EE   8
#define GG   4
#define PP   512
#define HH   192
#define PREDW 0.1

#define BM 64
#define BN 128
#define BK 16
#define ASTR 68          // As row stride (floats): bank = (4k+m)%32 -> <=2-way
#define BSTR 132         // Bs row stride: bank = (4k+n)%32 -> <=2-way
#define HS   68          // Hs row stride

// ---- device scratch ----
__device__ int   g_cnt[EE];
__device__ int   g_list[EE * BB];     // token + slot*8192
__device__ float g_wlist[EE * BB];
__device__ float g_scratch[(size_t)2 * BB * DD];   // per (token, slot) weighted expert output

__global__ void zero_cnt_kernel() {
    if (threadIdx.x < EE) g_cnt[threadIdx.x] = 0;
}

__device__ __forceinline__ float f2tf32(float v) {
    float o;
    asm("cvt.rna.tf32.f32 %0, %1;" : "=f"(o) : "f"(v));
    return o;
}

// m16n8k8 tf32 mma, C += A*B
__device__ __forceinline__ void mma8(float* c, const uint32_t* a, const uint32_t* b) {
    asm volatile(
        "mma.sync.aligned.m16n8k8.row.col.f32.tf32.tf32.f32 "
        "{%0,%1,%2,%3}, {%4,%5,%6,%7}, {%8,%9}, {%0,%1,%2,%3};"
        : "+f"(c[0]), "+f"(c[1]), "+f"(c[2]), "+f"(c[3])
        : "r"(a[0]), "r"(a[1]), "r"(a[2]), "r"(a[3]), "r"(b[0]), "r"(b[1]));
}

// ---------------- routing: proven R5 path (rel_err 9e-7) — unchanged ----------------
__global__ void routing_kernel(const float* __restrict__ x,
                               const float* __restrict__ Wg, const float* __restrict__ bg,
                               const float* __restrict__ Wp, const float* __restrict__ bp,
                               const float* __restrict__ Wgg, const float* __restrict__ bgg)
{
    int warp = threadIdx.x >> 5;
    int lane = threadIdx.x & 31;
    int b = blockIdx.x * 8 + warp;
    if (b >= BB) return;

    const float4* xr = (const float4*)(x + (size_t)b * DD);
    double s = 0.0;
#pragma unroll 4
    for (int i = lane; i < DD / 4; i += 32) {
        float4 v = xr[i];
        s += ((double)v.x + (double)v.y) + ((double)v.z + (double)v.w);
    }
#pragma unroll
    for (int o = 16; o; o >>= 1) s += __shfl_xor_sync(0xffffffffu, s, o);
    float qm = (float)(s * (1.0 / DD));

    double ts = 0.0;
#pragma unroll
    for (int j = 0; j < 6; j++) {
        float f = 7.0f * (float)(1 + lane + 32 * j);
        float angf = qm * f;
        double sn, cs;
        sincos((double)angf, &sn, &cs);
        ts += sn + cs;
    }
#pragma unroll
    for (int o = 16; o; o >>= 1) ts += __shfl_xor_sync(0xffffffffu, ts, o);

    if (lane != 0) return;

    double gi0 = ts * (1.0 / (2.0 * HH));
    double gi1 = 0.015625;

    double l[EE];
#pragma unroll
    for (int e = 0; e < EE; e++) {
        int g = e & 3;
        double v = gi0 * (double)Wg[e] + gi1 * (double)Wg[EE + e] + (double)bg[e];
        v -= PREDW * (gi0 * (double)Wp[e] + gi1 * (double)Wp[EE + e] + (double)bp[e]);
        v += gi0 * (double)Wgg[g] + gi1 * (double)Wgg[GG + g] + (double)bgg[g];
        l[e] = v;
    }
    double mx = l[0];
#pragma unroll
    for (int e = 1; e < EE; e++) mx = fmax(mx, l[e]);
    double p[EE], sum = 0.0;
#pragma unroll
    for (int e = 0; e < EE; e++) { p[e] = exp(l[e] - mx); sum += p[e]; }
    double inv = 1.0 / sum;
#pragma unroll
    for (int e = 0; e < EE; e++) p[e] *= inv;

    int i1 = 0;
#pragma unroll
    for (int e = 1; e < EE; e++) if (p[e] > p[i1]) i1 = e;
    int i2 = (i1 == 0) ? 1 : 0;
#pragma unroll
    for (int e = 0; e < EE; e++) if (e != i1 && p[e] > p[i2]) i2 = e;

    double denom = p[i1] + p[i2] + 1e-9;
    float w1 = (float)(p[i1] / denom);
    float w2 = (float)(p[i2] / denom);

    int pos = atomicAdd(&g_cnt[i1], 1);
    g_list [i1 * BB + pos] = b;
    g_wlist[i1 * BB + pos] = w1;
    pos = atomicAdd(&g_cnt[i2], 1);
    g_list [i2 * BB + pos] = b + BB;
    g_wlist[i2 * BB + pos] = w2;
}

// ---------- fused expert MLP via mma.sync tf32 (tensor pipe, compute_103-safe) ----------
__global__ __launch_bounds__(256, 1)
void expert_kernel(const float* __restrict__ x,
                   const float* __restrict__ W1, const float* __restrict__ b1,
                   const float* __restrict__ W2, const float* __restrict__ b2)
{
    int e = blockIdx.y;
    int cnt = g_cnt[e];
    int t0 = blockIdx.x * BM;
    if (t0 >= cnt) return;
    int ntok = min(BM, cnt - t0);

    extern __shared__ float Hs[];                  // [PP][HS], tf32-rounded relu(H)
    __shared__ float As[BK][ASTR];                 // A^T: As[k][m]
    __shared__ float Bs[BK][BSTR];                 // Bs[k][n]
    __shared__ int   s_tok[BM];
    __shared__ int   s_slot[BM];
    __shared__ float s_w[BM];

    int tid = threadIdx.x;
    int wid = tid >> 5, lane = tid & 31;
    int gid = lane >> 2, tig = lane & 3;           // mma fragment coords
    int mw = (wid & 1) * 32, nw = (wid >> 1) * 32; // warp tile origin (m, n)

    if (tid < BM) {
        int idx = (tid < ntok) ? (t0 + tid) : t0;
        int entry = g_list[e * BB + idx];
        s_tok[tid]  = entry & (BB - 1);
        s_slot[tid] = entry >> 13;
        s_w[tid]    = (tid < ntok) ? g_wlist[e * BB + idx] : 0.f;
    }
    __syncthreads();

    const float* W1e = W1 + (size_t)e * DD * PP;
    const float* b1e = b1 + e * PP;
    const float* W2e = W2 + (size_t)e * PP * DD;
    const float* b2e = b2 + e * DD;

    // A loader: thread -> (m = tid/4, k4 = (tid&3)*4)
    int la_m = tid >> 2;
    int la_k = (tid & 3) * 4;
    const float* xrow = x + (size_t)s_tok[la_m] * DD + la_k;
    // B loader: thread -> (k = tid/16, two float4 at n = lb_n*4 and 64+lb_n*4)
    int lb_k = tid >> 4;
    int lb_n = tid & 15;

    // ================= GEMM1: H = relu(X @ W1e + b1e) -> Hs (tf32) =================
    for (int nc = 0; nc < PP / BN; nc++) {
        float acc[2][4][4];
#pragma unroll
        for (int mt = 0; mt < 2; mt++)
#pragma unroll
            for (int nt = 0; nt < 4; nt++)
#pragma unroll
                for (int i = 0; i < 4; i++) acc[mt][nt][i] = 0.f;

        const float* Wbase = W1e + (size_t)lb_k * PP + nc * BN;
        for (int k0 = 0; k0 < DD; k0 += BK) {
            float4 av = *(const float4*)(xrow + k0);
            const float4* src = (const float4*)(Wbase + (size_t)k0 * PP);
            float4 bv0 = src[lb_n];
            float4 bv1 = src[16 + lb_n];
            __syncthreads();                       // prev tile fully consumed
            As[la_k + 0][la_m] = f2tf32(av.x);
            As[la_k + 1][la_m] = f2tf32(av.y);
            As[la_k + 2][la_m] = f2tf32(av.z);
            As[la_k + 3][la_m] = f2tf32(av.w);
            Bs[lb_k][lb_n * 4 + 0]      = f2tf32(bv0.x);
            Bs[lb_k][lb_n * 4 + 1]      = f2tf32(bv0.y);
            Bs[lb_k][lb_n * 4 + 2]      = f2tf32(bv0.z);
            Bs[lb_k][lb_n * 4 + 3]      = f2tf32(bv0.w);
            Bs[lb_k][64 + lb_n * 4 + 0] = f2tf32(bv1.x);
            Bs[lb_k][64 + lb_n * 4 + 1] = f2tf32(bv1.y);
            Bs[lb_k][64 + lb_n * 4 + 2] = f2tf32(bv1.z);
            Bs[lb_k][64 + lb_n * 4 + 3] = f2tf32(bv1.w);
            __syncthreads();
#pragma unroll
            for (int ks = 0; ks < 2; ks++) {
                int k8 = ks * 8;
                uint32_t a[2][4], b[4][2];
#pragma unroll
                for (int mt = 0; mt < 2; mt++) {
                    int m0 = mw + mt * 16 + gid;
                    a[mt][0] = __float_as_uint(As[k8 + tig][m0]);
                    a[mt][1] = __float_as_uint(As[k8 + tig][m0 + 8]);
                    a[mt][2] = __float_as_uint(As[k8 + tig + 4][m0]);
                    a[mt][3] = __float_as_uint(As[k8 + tig + 4][m0 + 8]);
                }
#pragma unroll
                for (int nt = 0; nt < 4; nt++) {
                    int n0 = nw + nt * 8 + gid;
                    b[nt][0] = __float_as_uint(Bs[k8 + tig][n0]);
                    b[nt][1] = __float_as_uint(Bs[k8 + tig + 4][n0]);
                }
#pragma unroll
                for (int mt = 0; mt < 2; mt++)
#pragma unroll
                    for (int nt = 0; nt < 4; nt++)
                        mma8(acc[mt][nt], a[mt], b[nt]);
            }
        }
        // epilogue: relu(+bias) -> Hs[p][m], tf32-rounded (conflict-free: bank = 8*tig+gid)
#pragma unroll
        for (int mt = 0; mt < 2; mt++)
#pragma unroll
            for (int nt = 0; nt < 4; nt++) {
                int p0  = nc * BN + nw + nt * 8 + tig * 2;
                int m0r = mw + mt * 16 + gid;
                float bb0 = b1e[p0], bb1 = b1e[p0 + 1];
                Hs[(p0)     * HS + m0r]     = f2tf32(fmaxf(acc[mt][nt][0] + bb0, 0.f));
                Hs[(p0 + 1) * HS + m0r]     = f2tf32(fmaxf(acc[mt][nt][1] + bb1, 0.f));
                Hs[(p0)     * HS + m0r + 8] = f2tf32(fmaxf(acc[mt][nt][2] + bb0, 0.f));
                Hs[(p0 + 1) * HS + m0r + 8] = f2tf32(fmaxf(acc[mt][nt][3] + bb1, 0.f));
            }
    }
    __syncthreads();   // all Hs columns written before GEMM2 reads

    // ================= GEMM2: out = (H @ W2e + b2e) * w -> g_scratch =================
    for (int nc = 0; nc < DD / BN; nc++) {
        float acc[2][4][4];
#pragma unroll
        for (int mt = 0; mt < 2; mt++)
#pragma unroll
            for (int nt = 0; nt < 4; nt++)
#pragma unroll
                for (int i = 0; i < 4; i++) acc[mt][nt][i] = 0.f;

        const float* Wbase = W2e + (size_t)lb_k * DD + nc * BN;
        for (int k0 = 0; k0 < PP; k0 += BK) {
            const float4* src = (const float4*)(Wbase + (size_t)k0 * DD);
            float4 bv0 = src[lb_n];
            float4 bv1 = src[16 + lb_n];
            __syncthreads();
            Bs[lb_k][lb_n * 4 + 0]      = f2tf32(bv0.x);
            Bs[lb_k][lb_n * 4 + 1]      = f2tf32(bv0.y);
            Bs[lb_k][lb_n * 4 + 2]      = f2tf32(bv0.z);
            Bs[lb_k][lb_n * 4 + 3]      = f2tf32(bv0.w);
            Bs[lb_k][64 + lb_n * 4 + 0] = f2tf32(bv1.x);
            Bs[lb_k][64 + lb_n * 4 + 1] = f2tf32(bv1.y);
            Bs[lb_k][64 + lb_n * 4 + 2] = f2tf32(bv1.z);
            Bs[lb_k][64 + lb_n * 4 + 3] = f2tf32(bv1.w);
            __syncthreads();
#pragma unroll
            for (int ks = 0; ks < 2; ks++) {
                int k8 = k0 + ks * 8;
                uint32_t a[2][4], b[4][2];
#pragma unroll
                for (int mt = 0; mt < 2; mt++) {
                    int m0 = mw + mt * 16 + gid;
                    a[mt][0] = __float_as_uint(Hs[(k8 + tig) * HS + m0]);
                    a[mt][1] = __float_as_uint(Hs[(k8 + tig) * HS + m0 + 8]);
                    a[mt][2] = __float_as_uint(Hs[(k8 + tig + 4) * HS + m0]);
                    a[mt][3] = __float_as_uint(Hs[(k8 + tig + 4) * HS + m0 + 8]);
                }
#pragma unroll
                for (int nt = 0; nt < 4; nt++) {
                    int n0 = nw + nt * 8 + gid;
                    b[nt][0] = __float_as_uint(Bs[ks * 8 + tig][n0]);
                    b[nt][1] = __float_as_uint(Bs[ks * 8 + tig + 4][n0]);
                }
#pragma unroll
                for (int mt = 0; mt < 2; mt++)
#pragma unroll
                    for (int nt = 0; nt < 4; nt++)
                        mma8(acc[mt][nt], a[mt], b[nt]);
            }
        }
        // epilogue: (+bias)*gate -> scratch rows (float2 per fragment pair)
#pragma unroll
        for (int mt = 0; mt < 2; mt++)
#pragma unroll
            for (int nt = 0; nt < 4; nt++) {
                int n0  = nc * BN + nw + nt * 8 + tig * 2;
                int m0r = mw + mt * 16 + gid;
                float bb0 = b2e[n0], bb1 = b2e[n0 + 1];
                if (m0r < ntok) {
                    float w = s_w[m0r];
                    size_t row = (size_t)(s_tok[m0r] * 2 + s_slot[m0r]) * DD + n0;
                    float2 o = { (acc[mt][nt][0] + bb0) * w, (acc[mt][nt][1] + bb1) * w };
                    *(float2*)&g_scratch[row] = o;
                }
                int m1r = m0r + 8;
                if (m1r < ntok) {
                    float w = s_w[m1r];
                    size_t row = (size_t)(s_tok[m1r] * 2 + s_slot[m1r]) * DD + n0;
                    float2 o = { (acc[mt][nt][2] + bb0) * w, (acc[mt][nt][3] + bb1) * w };
                    *(float2*)&g_scratch[row] = o;
                }
            }
    }
}

// ---------------- combine: out[b] = scr[b, slot0] + scr[b, slot1] ----------------
__global__ void combine_kernel(float* __restrict__ out)
{
    size_t i = (size_t)blockIdx.x * blockDim.x + threadIdx.x;
    size_t b = i / (DD / 4);
    size_t c = i - b * (DD / 4);
    const float4* s = (const float4*)g_scratch;
    float4 a0 = s[(2 * b)     * (DD / 4) + c];
    float4 a1 = s[(2 * b + 1) * (DD / 4) + c];
    float4 o;
    o.x = a0.x + a1.x; o.y = a0.y + a1.y; o.z = a0.z + a1.z; o.w = a0.w + a1.w;
    ((float4*)out)[i] = o;
}

extern "C" void kernel_launch(void* const* d_in, const int* in_sizes, int n_in,
                              void* d_out, int out_size)
{
    const float* x   = (const float*)d_in[0];
    const float* Wg  = (const float*)d_in[1];
    const float* bg  = (const float*)d_in[2];
    const float* Wp  = (const float*)d_in[3];
    const float* bp  = (const float*)d_in[4];
    const float* Wgg = (const float*)d_in[5];
    const float* bgg = (const float*)d_in[6];
    const float* W1  = (const float*)d_in[7];
    const float* b1  = (const float*)d_in[8];
    const float* W2  = (const float*)d_in[9];
    const float* b2  = (const float*)d_in[10];
    float* out = (float*)d_out;

    cudaFuncSetAttribute(expert_kernel, cudaFuncAttributeMaxDynamicSharedMemorySize,
                         PP * HS * (int)sizeof(float));

    zero_cnt_kernel<<<1, 32>>>();
    routing_kernel<<<BB / 8, 256>>>(x, Wg, bg, Wp, bp, Wgg, bgg);
    expert_kernel<<<dim3(BB / BM, EE), 256, PP * HS * sizeof(float)>>>(x, W1, b1, W2, b2);
    combine_kernel<<<(BB * (DD / 4)) / 256, 256>>>(out);
    (void)in_sizes; (void)n_in; (void)out_size;
}